// round 2
// baseline (speedup 1.0000x reference)
#include <cuda_runtime.h>

#define BB 16
#define GG 50
#define AA 81920
#define TT 128
#define PP 64
#define NNEGK 64
#define POSCAP 65536
#define HICAP 4096
#define HITHRESH 0.998f

// ---------------- device scratch (static, no allocation) ----------------
static __device__ float              g_colmax[BB][AA];
static __device__ float              g_nscore[BB][AA];
static __device__ unsigned int       g_rowmax[BB][GG];
static __device__ unsigned long long g_lkey[BB][GG];
static __device__ unsigned long long g_rkey[BB][GG];
static __device__ int                g_poscnt[BB];
static __device__ int                g_posj[BB][POSCAP];
static __device__ float              g_posu[BB][POSCAP];
static __device__ int                g_hicnt[BB];
static __device__ float              g_hiv[BB][HICAP];
static __device__ int                g_hii[BB][HICAP];
static __device__ uint2              g_key1[BB];
static __device__ uint2              g_key2[BB];

// ---------------- threefry2x32 (JAX-compatible) ----------------
__device__ __forceinline__ void threefry2x32(unsigned int k0, unsigned int k1,
                                             unsigned int x0, unsigned int x1,
                                             unsigned int &o0, unsigned int &o1) {
  const unsigned int ks0 = k0, ks1 = k1, ks2 = k0 ^ k1 ^ 0x1BD11BDAu;
  unsigned int v0 = x0 + ks0, v1 = x1 + ks1;
#define TFR(r) { v0 += v1; v1 = (v1 << (r)) | (v1 >> (32 - (r))); v1 ^= v0; }
  TFR(13) TFR(15) TFR(26) TFR(6)   v0 += ks1; v1 += ks2 + 1u;
  TFR(17) TFR(29) TFR(16) TFR(24)  v0 += ks2; v1 += ks0 + 2u;
  TFR(13) TFR(15) TFR(26) TFR(6)   v0 += ks0; v1 += ks1 + 3u;
  TFR(17) TFR(29) TFR(16) TFR(24)  v0 += ks1; v1 += ks2 + 4u;
  TFR(13) TFR(15) TFR(26) TFR(6)   v0 += ks2; v1 += ks0 + 5u;
#undef TFR
  o0 = v0; o1 = v1;
}

// partitionable-threefry 32-bit random_bits -> uniform [0,1)
__device__ __forceinline__ float jax_uniform(uint2 key, unsigned int idx) {
  unsigned int o0, o1;
  threefry2x32(key.x, key.y, 0u, idx, o0, o1);
  unsigned int bits = o0 ^ o1;
  return __uint_as_float((bits >> 9) | 0x3F800000u) - 1.0f;
}

// ---------------- init: reset reducers, derive per-image keys ----------------
__global__ void k_init() {
  const int t = threadIdx.x;
  for (int i = t; i < BB * GG; i += blockDim.x) {
    (&g_rowmax[0][0])[i] = 0u;
    (&g_lkey[0][0])[i]   = 0xFFFFFFFFFFFFFFFFull;
    (&g_rkey[0][0])[i]   = 0ull;
  }
  if (t < BB) {
    g_poscnt[t] = 0;
    g_hicnt[t]  = 0;
    // keys = split(key(42), 16)  (partitionable/foldlike)
    unsigned int kb0, kb1;
    threefry2x32(0u, 42u, 0u, (unsigned int)t, kb0, kb1);
    // k1, k2 = split(key_b)
    unsigned int a0, a1, c0, c1;
    threefry2x32(kb0, kb1, 0u, 0u, a0, a1);
    threefry2x32(kb0, kb1, 0u, 1u, c0, c1);
    g_key1[t] = make_uint2(a0, a1);
    g_key2[t] = make_uint2(c0, c1);
  }
}

// ---------------- pass A: column max (per anchor) + row max ----------------
__global__ void kA(const float* __restrict__ gt_boxes, const float* __restrict__ anchors) {
  const int b = blockIdx.y;
  const int a = blockIdx.x * blockDim.x + threadIdx.x;
  __shared__ float sq[GG][4];
  __shared__ float sarea[GG];
  __shared__ int   s_tg[GG];
  __shared__ int   s_nt;
  __shared__ unsigned int s_rm[GG];
  if (threadIdx.x == 0) s_nt = 0;
  __syncthreads();
  for (int g = threadIdx.x; g < GG; g += blockDim.x) {
    const float* p = gt_boxes + ((long)b * GG + g) * 5;
    float q0 = p[0], q1 = p[1], q2 = p[2], q3 = p[3], tg = p[4];
    sq[g][0] = q0; sq[g][1] = q1; sq[g][2] = q2; sq[g][3] = q3;
    sarea[g] = __fmul_rn(__fsub_rn(q3, q1), __fsub_rn(q2, q0));
    s_rm[g] = 0u;
    if (tg > 0.0f) { int k = atomicAdd(&s_nt, 1); s_tg[k] = g; }
  }
  __syncthreads();
  // anchors: [y1, x1, y2, x2]
  const float4 an = *reinterpret_cast<const float4*>(anchors + ((long)b * AA + a) * 4);
  const float areaa = __fmul_rn(__fsub_rn(an.w, an.y), __fsub_rn(an.z, an.x));
  float cm = 0.0f;
  const int nt = s_nt;
  for (int k = 0; k < nt; k++) {
    int g = s_tg[k];
    float iw = fmaxf(0.0f, __fsub_rn(fminf(sq[g][3], an.w), fmaxf(sq[g][1], an.y)));
    float ih = fmaxf(0.0f, __fsub_rn(fminf(sq[g][2], an.z), fmaxf(sq[g][0], an.x)));
    float inter = __fmul_rn(iw, ih);
    if (inter > 0.0f) {
      float v = __fdiv_rn(inter, __fsub_rn(__fadd_rn(sarea[g], areaa), inter));
      cm = fmaxf(cm, v);
      atomicMax(&s_rm[g], __float_as_uint(v));
    }
  }
  g_colmax[b][a] = cm;
  __syncthreads();
  for (int g = threadIdx.x; g < GG; g += blockDim.x)
    if (s_rm[g]) atomicMax(&g_rowmax[b][g], s_rm[g]);
}

// ---------------- pass B: pos pairs, left/right keys, negatives ----------------
__global__ void kB(const float* __restrict__ gt_boxes, const float* __restrict__ anchors) {
  const int b = blockIdx.y;
  const int a = blockIdx.x * blockDim.x + threadIdx.x;
  __shared__ float sq[GG][4];
  __shared__ float sarea[GG];
  __shared__ float s_rmf[GG];
  __shared__ int   s_tg[GG];
  __shared__ int   s_nt;
  if (threadIdx.x == 0) s_nt = 0;
  __syncthreads();
  for (int g = threadIdx.x; g < GG; g += blockDim.x) {
    const float* p = gt_boxes + ((long)b * GG + g) * 5;
    float q0 = p[0], q1 = p[1], q2 = p[2], q3 = p[3], tg = p[4];
    sq[g][0] = q0; sq[g][1] = q1; sq[g][2] = q2; sq[g][3] = q3;
    sarea[g] = __fmul_rn(__fsub_rn(q3, q1), __fsub_rn(q2, q0));
    s_rmf[g] = __uint_as_float(g_rowmax[b][g]);
    if (tg > 0.0f) { int k = atomicAdd(&s_nt, 1); s_tg[k] = g; }
  }
  __syncthreads();
  const float4 an = *reinterpret_cast<const float4*>(anchors + ((long)b * AA + a) * 4);
  const float areaa = __fmul_rn(__fsub_rn(an.w, an.y), __fsub_rn(an.z, an.x));
  const float cm = g_colmax[b][a];
  const float athr = (cm >= 0.7f) ? cm : 1.0f;
  const uint2 k1 = g_key1[b];
  bool anypos = false;
  const int nt = s_nt;
  for (int k = 0; k < nt; k++) {
    int g = s_tg[k];
    float iw = fmaxf(0.0f, __fsub_rn(fminf(sq[g][3], an.w), fmaxf(sq[g][1], an.y)));
    float ih = fmaxf(0.0f, __fsub_rn(fminf(sq[g][2], an.z), fmaxf(sq[g][0], an.x)));
    float inter = __fmul_rn(iw, ih);
    float v = 0.0f;
    if (inter > 0.0f)
      v = __fdiv_rn(inter, __fsub_rn(__fadd_rn(sarea[g], areaa), inter));
    if (v == s_rmf[g] || v == athr) {   // pos_mat(g, a) (tagged rows only)
      anypos = true;
      unsigned int j = (unsigned int)g * AA + (unsigned int)a;
      float u = jax_uniform(k1, j);
      int idx = atomicAdd(&g_poscnt[b], 1);
      if (idx < POSCAP) { g_posj[b][idx] = (int)j; g_posu[b][idx] = u; }
      unsigned long long xb = (unsigned long long)__float_as_uint(an.y); // x1 >= 0
      atomicMin(&g_lkey[b][g], (xb << 32) | (unsigned long long)(unsigned int)a);
      atomicMax(&g_rkey[b][g], (xb << 32) | (unsigned long long)(0xFFFFFFFFu - (unsigned int)a));
    }
  }
  float ns = -1.0f;
  if (cm < 0.5f && !anypos) {
    ns = jax_uniform(g_key2[b], (unsigned int)a);
    if (ns >= HITHRESH) {
      int idx = atomicAdd(&g_hicnt[b], 1);
      if (idx < HICAP) { g_hiv[b][idx] = ns; g_hii[b][idx] = a; }
    }
  }
  g_nscore[b][a] = ns;
}

// top-k by (value desc, index asc), matching lax.top_k tie-breaking.
// idxarr == nullptr -> use position i as index. Entries with val < 0 are skipped.
__device__ void topk_select(const float* val, const int* idxarr, int cnt, int k,
                            int* out_sel, unsigned long long* s_red, int t) {
  unsigned long long prev = 0xFFFFFFFFFFFFFFFFull;
  for (int s = 0; s < k; s++) {
    unsigned long long best = 0ull;
    for (int i = t; i < cnt; i += 256) {
      float v = val[i];
      if (v < 0.0f) continue;
      unsigned int id = idxarr ? (unsigned int)idxarr[i] : (unsigned int)i;
      unsigned long long key = ((unsigned long long)__float_as_uint(v) << 32)
                             | (unsigned long long)(0xFFFFFFFFu - id);
      if (key < prev && key > best) best = key;
    }
    s_red[t] = best;
    __syncthreads();
    for (int off = 128; off > 0; off >>= 1) {
      if (t < off && s_red[t + off] > s_red[t]) s_red[t] = s_red[t + off];
      __syncthreads();
    }
    prev = s_red[0];
    __syncthreads();
    if (t == 0) out_sel[s] = (int)(0xFFFFFFFFu - (unsigned int)(prev & 0xFFFFFFFFull));
  }
  __syncthreads();
}

// ---------------- pass C: selection + assembly (1 block / image) ----------------
__global__ void kC(const float* __restrict__ gt_boxes, const float* __restrict__ gt_cls,
                   const float* __restrict__ anchors, const int* __restrict__ vai,
                   float* __restrict__ out) {
  const int b = blockIdx.x;
  const int t = threadIdx.x;
  __shared__ unsigned long long s_red[256];
  __shared__ int   s_selj[PP];
  __shared__ float s_pd0[PP], s_pd1[PP], s_pc[PP];
  __shared__ int   s_ai[PP];
  __shared__ int   s_negi[NNEGK];

  // ---- positive top-64 ----
  int cnt = g_poscnt[b]; if (cnt > POSCAP) cnt = POSCAP;
  const int pos_num = cnt < PP ? cnt : PP;
  topk_select(g_posu[b], g_posj[b], cnt, pos_num, s_selj, s_red, t);

  for (int s = t; s < pos_num; s += 256) {
    int j = s_selj[s];
    int g = j / AA;
    int a = j - g * AA;
    const float* pa = anchors + ((long)b * AA + a) * 4;
    const float* pg = gt_boxes + ((long)b * GG + g) * 5;
    float h   = pa[2] - pa[0];
    float gth = pg[2] - pg[0];
    float dy  = (pg[2] + pg[0] - (pa[2] + pa[0])) * 0.5f / h;
    float dh  = logf(gth / h);
    s_pd0[s] = dy / 0.1f;
    s_pd1[s] = dh / 0.2f;
    s_pc[s]  = gt_cls[((long)b * GG + g) * 2];
    s_ai[s]  = a;
  }
  __syncthreads();

  // ---- negative top-64 ----
  int hic = g_hicnt[b]; if (hic > HICAP) hic = HICAP;
  int neg_num;
  if (hic >= NNEGK) {
    neg_num = NNEGK;  // avail >= 64 and T - pos_num >= 64
    topk_select(g_hiv[b], g_hii[b], hic, NNEGK, s_negi, s_red, t);
  } else {
    int av = 0;
    for (int i = t; i < AA; i += 256) if (g_nscore[b][i] >= 0.0f) av++;
    s_red[t] = (unsigned long long)av;
    __syncthreads();
    for (int off = 128; off > 0; off >>= 1) {
      if (t < off) s_red[t] += s_red[t + off];
      __syncthreads();
    }
    int avail = (int)s_red[0];
    __syncthreads();
    neg_num = avail < NNEGK ? avail : NNEGK;
    if (neg_num > TT - pos_num) neg_num = TT - pos_num;
    topk_select(g_nscore[b], nullptr, AA, neg_num, s_negi, s_red, t);
  }

  // ---- assembly (flat float32 output, concatenated in tuple order) ----
  const int OFF_DELTAS = 0;
  const int OFF_CLS = BB * TT * 3;
  const int OFF_IND = OFF_CLS + BB * TT * 2;
  const int OFF_SD  = OFF_IND + BB * TT * 2;
  const int OFF_SI  = OFF_SD + BB * GG * 3;
  const int OFF_GTN = OFF_SI + BB * GG * 3;
  const int OFF_PN  = OFF_GTN + BB;
  const int OFF_NN  = OFF_PN + BB;

  for (int i = t; i < TT; i += 256) {
    bool isp = i < pos_num;
    bool isn = !isp && (i < pos_num + neg_num);
    float tagc = (isp || isn) ? 1.0f : 0.0f;
    float* dd = out + OFF_DELTAS + ((long)b * TT + i) * 3;
    dd[0] = isp ? s_pd0[i] : 0.0f;
    dd[1] = isp ? s_pd1[i] : 0.0f;
    dd[2] = tagc;
    float* dc = out + OFF_CLS + ((long)b * TT + i) * 2;
    dc[0] = isp ? s_pc[i] : 0.0f;
    dc[1] = tagc;
    int ind = 0;
    if (isp)      ind = vai[(long)b * AA + s_ai[i]];
    else if (isn) ind = s_negi[i - pos_num];
    float* di = out + OFF_IND + ((long)b * TT + i) * 2;
    di[0] = (float)ind;
    di[1] = isp ? 1.0f : (isn ? -1.0f : 0.0f);
  }

  for (int g = t; g < GG; g += 256) {
    const float* pg = gt_boxes + ((long)b * GG + g) * 5;
    float* sd = out + OFF_SD + ((long)b * GG + g) * 3;
    float* si = out + OFF_SI + ((long)b * GG + g) * 3;
    if (pg[4] > 0.0f) {
      unsigned long long lk = g_lkey[b][g];
      unsigned long long rk = g_rkey[b][g];
      int la_i = (int)(unsigned int)(lk & 0xFFFFFFFFull);
      int ra_i = (int)(0xFFFFFFFFu - (unsigned int)(rk & 0xFFFFFFFFull));
      const float* la = anchors + ((long)b * AA + la_i) * 4;
      const float* ra = anchors + ((long)b * AA + ra_i) * 4;
      float ld = (pg[1] - (la[3] + la[1]) * 0.5f) / (la[3] - la[1]) / 0.1f;
      float rd = (pg[3] - (ra[3] + ra[1]) * 0.5f) / (ra[3] - ra[1]) / 0.1f;
      sd[0] = ld; sd[1] = rd; sd[2] = 1.0f;
      si[0] = (float)vai[(long)b * AA + la_i];
      si[1] = (float)vai[(long)b * AA + ra_i];
      si[2] = 1.0f;
    } else {
      sd[0] = 0.0f; sd[1] = 0.0f; sd[2] = 0.0f;
      si[0] = 0.0f; si[1] = 0.0f; si[2] = 0.0f;
    }
  }

  if (t == 0) {
    float gtn = 0.0f;
    for (int g = 0; g < GG; g++)
      if (gt_boxes[((long)b * GG + g) * 5 + 4] > 0.0f) gtn += 1.0f;
    out[OFF_GTN + b] = gtn;
    out[OFF_PN + b]  = (float)pos_num;
    out[OFF_NN + b]  = (float)neg_num;
  }
}

extern "C" void kernel_launch(void* const* d_in, const int* in_sizes, int n_in,
                              void* d_out, int out_size) {
  const float* gt_boxes = (const float*)d_in[0];   // (B, 50, 5)
  const float* gt_cls   = (const float*)d_in[1];   // (B, 50, 2)
  const float* anchors  = (const float*)d_in[2];   // (B, 81920, 4)
  const int*   vai      = (const int*)d_in[3];     // (B, 81920)
  float* out = (float*)d_out;

  k_init<<<1, 256>>>();
  dim3 gridAB(AA / 256, BB);
  kA<<<gridAB, 256>>>(gt_boxes, anchors);
  kB<<<gridAB, 256>>>(gt_boxes, anchors);
  kC<<<BB, 256>>>(gt_boxes, gt_cls, anchors, vai, out);
}

// round 4
// speedup vs baseline: 1.6104x; 1.6104x over previous
#include <cuda_runtime.h>

#define BB 16
#define GG 50
#define AA 81920
#define TT 128
#define PP 64
#define NNEGK 64
#define POSCAP 65536
#define HICAP 4096
#define HITHRESH 0.998f
#define NBK 512
#define CAP 2048

// ---------------- device scratch (static, no allocation) ----------------
static __device__ float              g_colmax[BB][AA];
static __device__ int                g_argg[BB][AA];      // written only when cm>=0.7
static __device__ unsigned long long g_rowvk[BB][GG];     // (v_bits<<32)|(~a)
static __device__ unsigned long long g_lx[BB][GG];        // (x1_bits<<32)|a   (atomicMin)
static __device__ unsigned long long g_rx[BB][GG];        // (x1_bits<<32)|(~a) (atomicMax)
static __device__ int                g_poscnt[BB];
static __device__ int                g_posj[BB][POSCAP];
static __device__ float              g_posu[BB][POSCAP];
static __device__ int                g_hicnt[BB];
static __device__ float              g_hiv[BB][HICAP];
static __device__ int                g_hii[BB][HICAP];
static __device__ int                g_stalecnt[BB];
static __device__ int                g_stale[BB][64];
static __device__ int                g_negavail[BB];
static __device__ float              g_fbu[BB][AA];       // fallback-only scratch
static __device__ uint2              g_key1[BB];
static __device__ uint2              g_key2[BB];

// ---------------- threefry2x32 (JAX partitionable) ----------------
__device__ __forceinline__ void threefry2x32(unsigned int k0, unsigned int k1,
                                             unsigned int x0, unsigned int x1,
                                             unsigned int &o0, unsigned int &o1) {
  const unsigned int ks0 = k0, ks1 = k1, ks2 = k0 ^ k1 ^ 0x1BD11BDAu;
  unsigned int v0 = x0 + ks0, v1 = x1 + ks1;
#define TFR(r) { v0 += v1; v1 = (v1 << (r)) | (v1 >> (32 - (r))); v1 ^= v0; }
  TFR(13) TFR(15) TFR(26) TFR(6)   v0 += ks1; v1 += ks2 + 1u;
  TFR(17) TFR(29) TFR(16) TFR(24)  v0 += ks2; v1 += ks0 + 2u;
  TFR(13) TFR(15) TFR(26) TFR(6)   v0 += ks0; v1 += ks1 + 3u;
  TFR(17) TFR(29) TFR(16) TFR(24)  v0 += ks1; v1 += ks2 + 4u;
  TFR(13) TFR(15) TFR(26) TFR(6)   v0 += ks2; v1 += ks0 + 5u;
#undef TFR
  o0 = v0; o1 = v1;
}

__device__ __forceinline__ float jax_uniform(uint2 key, unsigned int idx) {
  unsigned int o0, o1;
  threefry2x32(key.x, key.y, 0u, idx, o0, o1);
  unsigned int bits = o0 ^ o1;
  return __uint_as_float((bits >> 9) | 0x3F800000u) - 1.0f;
}

// ---------------- init ----------------
__global__ void k_init() {
  const int t = threadIdx.x;
  for (int i = t; i < BB * GG; i += blockDim.x) {
    (&g_rowvk[0][0])[i] = 0ull;
    (&g_lx[0][0])[i]    = 0xFFFFFFFFFFFFFFFFull;
    (&g_rx[0][0])[i]    = 0ull;
  }
  if (t < BB) {
    g_poscnt[t] = 0; g_hicnt[t] = 0; g_stalecnt[t] = 0; g_negavail[t] = 0;
    unsigned int kb0, kb1;
    threefry2x32(0u, 42u, 0u, (unsigned int)t, kb0, kb1);
    unsigned int a0, a1, c0, c1;
    threefry2x32(kb0, kb1, 0u, 0u, a0, a1);
    threefry2x32(kb0, kb1, 0u, 1u, c0, c1);
    g_key1[t] = make_uint2(a0, a1);
    g_key2[t] = make_uint2(c0, c1);
  }
}

// ---------------- pass A: single pair-pass ----------------
__global__ void kA(const float* __restrict__ gt_boxes, const float* __restrict__ anchors) {
  const int b = blockIdx.y;
  const int a = blockIdx.x * blockDim.x + threadIdx.x;
  __shared__ float sq[GG][4];
  __shared__ float sarea[GG];
  __shared__ int   s_tg[GG];
  __shared__ int   s_nt;
  __shared__ unsigned long long s_rk[GG];  // row (v, ~a) key
  __shared__ unsigned long long s_lk[GG];  // left x1 key (col candidates)
  __shared__ unsigned long long s_rr[GG];  // right x1 key (col candidates)
  if (threadIdx.x == 0) s_nt = 0;
  __syncthreads();
  for (int g = threadIdx.x; g < GG; g += blockDim.x) {
    const float* p = gt_boxes + ((long)b * GG + g) * 5;
    float q0 = p[0], q1 = p[1], q2 = p[2], q3 = p[3], tg = p[4];
    sq[g][0] = q0; sq[g][1] = q1; sq[g][2] = q2; sq[g][3] = q3;
    sarea[g] = __fmul_rn(__fsub_rn(q3, q1), __fsub_rn(q2, q0));
    s_rk[g] = 0ull; s_lk[g] = 0xFFFFFFFFFFFFFFFFull; s_rr[g] = 0ull;
    if (tg > 0.0f) { int k = atomicAdd(&s_nt, 1); s_tg[k] = g; }
  }
  __syncthreads();
  const float4 an = *reinterpret_cast<const float4*>(anchors + ((long)b * AA + a) * 4);
  const float areaa = __fmul_rn(__fsub_rn(an.w, an.y), __fsub_rn(an.z, an.x));
  float cm = 0.0f;
  int gbest = 0;
  const int nt = s_nt;
  for (int k = 0; k < nt; k++) {
    int g = s_tg[k];
    float iw = fmaxf(0.0f, __fsub_rn(fminf(sq[g][3], an.w), fmaxf(sq[g][1], an.y)));
    float ih = fmaxf(0.0f, __fsub_rn(fminf(sq[g][2], an.z), fmaxf(sq[g][0], an.x)));
    float inter = __fmul_rn(iw, ih);
    if (inter > 0.0f) {
      float v = __fdiv_rn(inter, __fsub_rn(__fadd_rn(sarea[g], areaa), inter));
      if (v > cm) { cm = v; gbest = g; }
      unsigned long long key = ((unsigned long long)__float_as_uint(v) << 32)
                             | (unsigned long long)(0xFFFFFFFFu - (unsigned int)a);
      atomicMax(&s_rk[g], key);
    }
  }
  g_colmax[b][a] = cm;
  if (cm >= 0.7f) {
    g_argg[b][a] = gbest;
    unsigned int j = (unsigned int)gbest * AA + (unsigned int)a;
    float u = jax_uniform(g_key1[b], j);
    int idx = atomicAdd(&g_poscnt[b], 1);
    if (idx < POSCAP) { g_posj[b][idx] = (int)j; g_posu[b][idx] = u; }
    unsigned long long xb = (unsigned long long)__float_as_uint(an.y);
    atomicMin(&s_lk[gbest], (xb << 32) | (unsigned long long)(unsigned int)a);
    atomicMax(&s_rr[gbest], (xb << 32) | (unsigned long long)(0xFFFFFFFFu - (unsigned int)a));
  }
  // negative path (row-winner staleness corrected later in kRow)
  bool isneg = (cm < 0.5f);
  if (isneg) {
    float u = jax_uniform(g_key2[b], (unsigned int)a);
    if (u >= HITHRESH) {
      int idx = atomicAdd(&g_hicnt[b], 1);
      if (idx < HICAP) { g_hiv[b][idx] = u; g_hii[b][idx] = a; }
    }
  }
  int c = __syncthreads_count(isneg);
  if (threadIdx.x == 0) atomicAdd(&g_negavail[b], c);
  for (int g = threadIdx.x; g < GG; g += blockDim.x) {
    if (s_rk[g]) atomicMax(&g_rowvk[b][g], s_rk[g]);
    if (s_lk[g] != 0xFFFFFFFFFFFFFFFFull) atomicMin(&g_lx[b][g], s_lk[g]);
    if (s_rr[g]) atomicMax(&g_rx[b][g], s_rr[g]);
  }
}

// ---------------- kRow: row winners (≤50/image) ----------------
__global__ void kRow(const float* __restrict__ gt_boxes, const float* __restrict__ anchors) {
  const int b = blockIdx.x;
  const int g = threadIdx.x;
  if (g >= GG) return;
  if (gt_boxes[((long)b * GG + g) * 5 + 4] <= 0.0f) return;
  unsigned long long rk = g_rowvk[b][g];
  unsigned int a = 0xFFFFFFFFu - (unsigned int)(rk & 0xFFFFFFFFull);
  float cma = g_colmax[b][a];
  bool dup = (cma >= 0.7f) && (g_argg[b][a] == g);
  if (!dup) {
    unsigned int j = (unsigned int)g * AA + a;
    float u = jax_uniform(g_key1[b], j);
    int idx = atomicAdd(&g_poscnt[b], 1);
    if (idx < POSCAP) { g_posj[b][idx] = (int)j; g_posu[b][idx] = u; }
    unsigned long long xb =
      (unsigned long long)__float_as_uint(anchors[((long)b * AA + a) * 4 + 1]);
    atomicMin(&g_lx[b][g], (xb << 32) | (unsigned long long)a);
    atomicMax(&g_rx[b][g], (xb << 32) | (unsigned long long)(0xFFFFFFFFu - a));
  }
  if (cma < 0.5f) {   // this anchor wrongly entered the neg pool in kA
    int k = atomicAdd(&g_stalecnt[b], 1);
    if (k < 64) g_stale[b][k] = (int)a;
  }
}

// ---------------- block max of u64 via shuffles ----------------
__device__ __forceinline__ unsigned long long blk_max(unsigned long long v,
                                                      unsigned long long* s_part, int t) {
  for (int o = 16; o; o >>= 1) {
    unsigned long long w = __shfl_xor_sync(0xFFFFFFFFu, v, o);
    if (w > v) v = w;
  }
  if ((t & 31) == 0) s_part[t >> 5] = v;
  __syncthreads();
  if (t < 32) {
    unsigned long long w = (t < 8) ? s_part[t] : 0ull;
    for (int o = 4; o; o >>= 1) {
      unsigned long long x = __shfl_xor_sync(0xFFFFFFFFu, w, o);
      if (x > w) w = x;
    }
    if (t == 0) s_part[0] = w;
  }
  __syncthreads();
  unsigned long long r = s_part[0];
  __syncthreads();
  return r;
}

// top-k over shared compacted arrays (all entries valid)
__device__ void topk_sh(const float* su, const int* sj, int M, int k, int* out,
                        unsigned long long* s_part, int t) {
  unsigned long long prev = 0xFFFFFFFFFFFFFFFFull;
  for (int s = 0; s < k; s++) {
    unsigned long long best = 0ull;
    for (int i = t; i < M; i += 256) {
      unsigned long long key = ((unsigned long long)__float_as_uint(su[i]) << 32)
                             | (unsigned long long)(0xFFFFFFFFu - (unsigned int)sj[i]);
      if (key < prev && key > best) best = key;
    }
    best = blk_max(best, s_part, t);
    prev = best;
    if (t == 0) out[s] = (int)(0xFFFFFFFFu - (unsigned int)(best & 0xFFFFFFFFull));
  }
  __syncthreads();
}

// slow global top-k (fallback only); val<0 skipped; idxarr==null -> identity
__device__ void topk_gl(const float* val, const int* idxarr, int cnt, int k, int* out,
                        unsigned long long* s_part, int t) {
  unsigned long long prev = 0xFFFFFFFFFFFFFFFFull;
  for (int s = 0; s < k; s++) {
    unsigned long long best = 0ull;
    for (int i = t; i < cnt; i += 256) {
      float v = val[i];
      if (v < 0.0f) continue;
      unsigned int id = idxarr ? (unsigned int)idxarr[i] : (unsigned int)i;
      unsigned long long key = ((unsigned long long)__float_as_uint(v) << 32)
                             | (unsigned long long)(0xFFFFFFFFu - id);
      if (key < prev && key > best) best = key;
    }
    best = blk_max(best, s_part, t);
    prev = best;
    if (t == 0) out[s] = (int)(0xFFFFFFFFu - (unsigned int)(best & 0xFFFFFFFFull));
  }
  __syncthreads();
}

// ---------------- pass C: selection + assembly (1 block / image) ----------------
__global__ void kC(const float* __restrict__ gt_boxes, const float* __restrict__ gt_cls,
                   const float* __restrict__ anchors, const int* __restrict__ vai,
                   float* __restrict__ out) {
  const int b = blockIdx.x;
  const int t = threadIdx.x;
  __shared__ unsigned long long s_part[8];
  __shared__ int   s_hist[NBK];
  __shared__ float s_cu[CAP];
  __shared__ int   s_cj[CAP];
  __shared__ int   s_ctl[4];   // [0]=compact counter, [1]=threshold bucket, [2]=overflow flag
  __shared__ int   s_selj[PP];
  __shared__ float s_pd0[PP], s_pd1[PP], s_pc[PP];
  __shared__ int   s_ai[PP];
  __shared__ int   s_negi[NNEGK];
  __shared__ int   s_stale[64];

  // ======== positives ========
  int cnt = g_poscnt[b]; if (cnt > POSCAP) cnt = POSCAP;
  const int pos_num = cnt < PP ? cnt : PP;
  bool fb = false;
  int M = 0;
  if (cnt <= CAP) {
    for (int i = t; i < cnt; i += 256) { s_cu[i] = g_posu[b][i]; s_cj[i] = g_posj[b][i]; }
    M = cnt;
    __syncthreads();
  } else {
    for (int i = t; i < NBK; i += 256) s_hist[i] = 0;
    if (t == 0) { s_ctl[0] = 0; s_ctl[2] = 0; }
    __syncthreads();
    for (int i = t; i < cnt; i += 256) {
      int bk = (int)(g_posu[b][i] * (float)NBK);
      if (bk > NBK - 1) bk = NBK - 1;
      atomicAdd(&s_hist[bk], 1);
    }
    __syncthreads();
    if (t == 0) {
      int acc = 0, tb = 0;
      for (int i = NBK - 1; i >= 0; i--) { acc += s_hist[i]; if (acc >= PP) { tb = i; break; } }
      s_ctl[1] = tb;
      if (acc > CAP) s_ctl[2] = 1;
    }
    __syncthreads();
    if (s_ctl[2]) {
      fb = true;
    } else {
      int tb = s_ctl[1];
      for (int i = t; i < cnt; i += 256) {
        float u = g_posu[b][i];
        int bk = (int)(u * (float)NBK); if (bk > NBK - 1) bk = NBK - 1;
        if (bk >= tb) {
          int p = atomicAdd(&s_ctl[0], 1);
          s_cu[p] = u; s_cj[p] = g_posj[b][i];
        }
      }
      __syncthreads();
      M = s_ctl[0];
    }
  }
  if (!fb) topk_sh(s_cu, s_cj, M, pos_num, s_selj, s_part, t);
  else     topk_gl(g_posu[b], g_posj[b], cnt, pos_num, s_selj, s_part, t);

  for (int s = t; s < pos_num; s += 256) {
    int j = s_selj[s];
    int g = j / AA;
    int a = j - g * AA;
    const float* pa = anchors + ((long)b * AA + a) * 4;
    const float* pg = gt_boxes + ((long)b * GG + g) * 5;
    float h   = pa[2] - pa[0];
    float gth = pg[2] - pg[0];
    float dy  = (pg[2] + pg[0] - (pa[2] + pa[0])) * 0.5f / h;
    float dh  = logf(gth / h);
    s_pd0[s] = dy / 0.1f;
    s_pd1[s] = dh / 0.2f;
    s_pc[s]  = gt_cls[((long)b * GG + g) * 2];
    s_ai[s]  = a;
  }
  __syncthreads();

  // ======== negatives ========
  int sc = g_stalecnt[b]; if (sc > 64) sc = 64;
  for (int i = t; i < sc; i += 256) s_stale[i] = g_stale[b][i];
  if (t == 0) { s_ctl[0] = 0; s_ctl[2] = 0; }
  __syncthreads();
  int hic = g_hicnt[b]; if (hic > HICAP) hic = HICAP;
  for (int i = t; i < hic; i += 256) {
    int a = g_hii[b][i];
    bool ok = true;
    for (int k = 0; k < sc; k++) if (s_stale[k] == a) { ok = false; break; }
    if (ok) {
      int p = atomicAdd(&s_ctl[0], 1);
      if (p < CAP) { s_cu[p] = g_hiv[b][i]; s_cj[p] = a; }
      else s_ctl[2] = 1;
    }
  }
  __syncthreads();
  int hice = s_ctl[0]; if (hice > CAP) hice = CAP;
  int neg_num;
  if (hice >= NNEGK && !s_ctl[2]) {
    neg_num = NNEGK;
    topk_sh(s_cu, s_cj, hice, NNEGK, s_negi, s_part, t);
  } else {
    int avail = g_negavail[b] - sc;
    neg_num = avail < NNEGK ? avail : NNEGK;
    if (neg_num > TT - pos_num) neg_num = TT - pos_num;
    if (neg_num < 0) neg_num = 0;
    // rebuild full neg score array (rare path)
    const uint2 k2 = g_key2[b];
    for (int a = t; a < AA; a += 256) {
      float ns = -1.0f;
      if (g_colmax[b][a] < 0.5f) {
        bool ok = true;
        for (int k = 0; k < sc; k++) if (s_stale[k] == a) { ok = false; break; }
        if (ok) ns = jax_uniform(k2, (unsigned int)a);
      }
      g_fbu[b][a] = ns;
    }
    __syncthreads();
    topk_gl(g_fbu[b], nullptr, AA, neg_num, s_negi, s_part, t);
  }

  // ======== assembly ========
  const int OFF_DELTAS = 0;
  const int OFF_CLS = BB * TT * 3;
  const int OFF_IND = OFF_CLS + BB * TT * 2;
  const int OFF_SD  = OFF_IND + BB * TT * 2;
  const int OFF_SI  = OFF_SD + BB * GG * 3;
  const int OFF_GTN = OFF_SI + BB * GG * 3;
  const int OFF_PN  = OFF_GTN + BB;
  const int OFF_NN  = OFF_PN + BB;

  for (int i = t; i < TT; i += 256) {
    bool isp = i < pos_num;
    bool isn = !isp && (i < pos_num + neg_num);
    float tagc = (isp || isn) ? 1.0f : 0.0f;
    float* dd = out + OFF_DELTAS + ((long)b * TT + i) * 3;
    dd[0] = isp ? s_pd0[i] : 0.0f;
    dd[1] = isp ? s_pd1[i] : 0.0f;
    dd[2] = tagc;
    float* dc = out + OFF_CLS + ((long)b * TT + i) * 2;
    dc[0] = isp ? s_pc[i] : 0.0f;
    dc[1] = tagc;
    int ind = 0;
    if (isp)      ind = vai[(long)b * AA + s_ai[i]];
    else if (isn) ind = s_negi[i - pos_num];
    float* di = out + OFF_IND + ((long)b * TT + i) * 2;
    di[0] = (float)ind;
    di[1] = isp ? 1.0f : (isn ? -1.0f : 0.0f);
  }

  for (int g = t; g < GG; g += 256) {
    const float* pg = gt_boxes + ((long)b * GG + g) * 5;
    float* sd = out + OFF_SD + ((long)b * GG + g) * 3;
    float* si = out + OFF_SI + ((long)b * GG + g) * 3;
    if (pg[4] > 0.0f) {
      unsigned long long lk = g_lx[b][g];
      unsigned long long rk = g_rx[b][g];
      int la_i = (int)(unsigned int)(lk & 0xFFFFFFFFull);
      int ra_i = (int)(0xFFFFFFFFu - (unsigned int)(rk & 0xFFFFFFFFull));
      const float* la = anchors + ((long)b * AA + la_i) * 4;
      const float* ra = anchors + ((long)b * AA + ra_i) * 4;
      float ld = (pg[1] - (la[3] + la[1]) * 0.5f) / (la[3] - la[1]) / 0.1f;
      float rd = (pg[3] - (ra[3] + ra[1]) * 0.5f) / (ra[3] - ra[1]) / 0.1f;
      sd[0] = ld; sd[1] = rd; sd[2] = 1.0f;
      si[0] = (float)vai[(long)b * AA + la_i];
      si[1] = (float)vai[(long)b * AA + ra_i];
      si[2] = 1.0f;
    } else {
      sd[0] = 0.0f; sd[1] = 0.0f; sd[2] = 0.0f;
      si[0] = 0.0f; si[1] = 0.0f; si[2] = 0.0f;
    }
  }

  if (t == 0) {
    float gtn = 0.0f;
    for (int g = 0; g < GG; g++)
      if (gt_boxes[((long)b * GG + g) * 5 + 4] > 0.0f) gtn += 1.0f;
    out[OFF_GTN + b] = gtn;
    out[OFF_PN + b]  = (float)pos_num;
    out[OFF_NN + b]  = (float)neg_num;
  }
}

extern "C" void kernel_launch(void* const* d_in, const int* in_sizes, int n_in,
                              void* d_out, int out_size) {
  const float* gt_boxes = (const float*)d_in[0];   // (B, 50, 5)
  const float* gt_cls   = (const float*)d_in[1];   // (B, 50, 2)
  const float* anchors  = (const float*)d_in[2];   // (B, 81920, 4)
  const int*   vai      = (const int*)d_in[3];     // (B, 81920)
  float* out = (float*)d_out;

  k_init<<<1, 256>>>();
  dim3 gridA(AA / 256, BB);
  kA<<<gridA, 256>>>(gt_boxes, anchors);
  kRow<<<BB, 64>>>(gt_boxes, anchors);
  kC<<<BB, 256>>>(gt_boxes, gt_cls, anchors, vai, out);
}